// round 15
// baseline (speedup 1.0000x reference)
#include <cuda_runtime.h>
#include <cuda_bf16.h>

// Semi-CRF forward DP (HSCRF). B=16, L=128, T=11, K=7.
// R15: leader-dot step, zero SHFL / zero MUFU on the critical path.
// Linear-domain publish (S rows, per-slot log2 scale; R13-proven exact):
// in slot e every lane STSes its k<=5 partial and its f6 factor for step e+1
// into double-buffered smem rows; after the barrier the segment leader
// computes S_{e+1}[y] = sum_yp (S_e[yp]*F6[yp] + P[yp]) with 9 LDS.128 +
// FMA tree and publishes. 192 thr, x8 unroll (compile-time slots), depth-3
// prefetch, branch-free masking, in-kernel final reduction.

#define B_ 16
#define L_ 128
#define T_ 11
#define K_ 7
#define TT_ 121
#define NEGBIG  (-1e30f)
#define LOG2E_F 1.4426950408889634f
#define LN2_F   0.6931471805599453f
#define STEP_EL (129 * TT_)   /* elem offset per end-position step: 15609 */
#define KOFF_EL (128 * TT_)   /* elem offset per k: 15488 */

__device__ float g_partial[B_];
__device__ unsigned int g_tickets;   // one winner per launch (16 arrivals)

__device__ __forceinline__ float ex2f(float x) {
    float r; asm("ex2.approx.ftz.f32 %0, %1;" : "=f"(r) : "f"(x)); return r;
}
__device__ __forceinline__ float lg2f(float x) {
    float r; asm("lg2.approx.f32 %0, %1;" : "=f"(r) : "f"(x)); return r;
}

// One DP step at e = eb + U (computes S_{e+1} with scale Mcur).
// PFMODE 0: first block (compile-time j>=0 masks on prefetch)
//        1: steady state (no masks)
//        2: last block (skip prefetch when e+3 >= L_, compile-time)
#define DP_STEP(U, PFMODE)                                                     \
    do {                                                                       \
        /* ── post-barrier critical path: leaders only, no SHFL/MUFU ── */     \
        if (yp == 0 && y < T_) {                                               \
            const float4* Srow = reinterpret_cast<const float4*>(s_Sring[(U)]);\
            const float4* Frow =                                               \
                reinterpret_cast<const float4*>(s_F6[(U) & 1][y]);             \
            const float4* Prow =                                               \
                reinterpret_cast<const float4*>(s_P[(U) & 1][y]);              \
            float4 s0 = Srow[0], s1 = Srow[1], s2 = Srow[2];                   \
            float4 f0 = Frow[0], f1 = Frow[1], f2 = Frow[2];                   \
            float4 q0 = Prow[0], q1 = Prow[1], q2 = Prow[2];                   \
            float d0 = fmaf(s0.x, f0.x, q0.x) + fmaf(s1.x, f1.x, q1.x);        \
            float d1 = fmaf(s0.y, f0.y, q0.y) + fmaf(s1.y, f1.y, q1.y);        \
            float d2 = fmaf(s0.z, f0.z, q0.z) + fmaf(s1.z, f1.z, q1.z);        \
            float d3 = fmaf(s0.w, f0.w, q0.w) + fmaf(s1.w, f1.w, q1.w);        \
            d0 += fmaf(s2.x, f2.x, q2.x);                                      \
            d1 += fmaf(s2.y, f2.y, q2.y);                                      \
            d2 += fmaf(s2.z, f2.z, q2.z);                                      \
            d3 += fmaf(s2.w, f2.w, q2.w);                                      \
            float Sn = (d0 + d1) + (d2 + d3);                                  \
            s_Sring[((U) + 1) & 7][y] = Sn;      /* publish first */           \
            if (y == 0) s_r[((U) + 1) & 7] = Mcur + lg2f(Sn);                  \
            if (y == T_ - 2 && (eb + (U) + 1) == len)                          \
                res = Mcur + lg2f(Sn);                                         \
        }                                                                      \
        /* ── filler: scales, window, prefetch, factors for step e+1 ── */     \
        const float Mn = s_r[((U) + 7) & 7];     /* alpha_{e-1}[0] */          \
        _Pragma("unroll")                                                      \
        for (int k = 0; k < K_ - 1; k++) {                                     \
            av[k] = av[k + 1]; msc[k] = msc[k + 1];                            \
        }                                                                      \
        av[K_ - 1]  = s_Sring[(U)][yp];          /* S_e[yp] */                 \
        msc[K_ - 1] = Mprev;                     /* scale of S_e */            \
        if ((PFMODE) != 2 || (U) < 5) {                                        \
            _Pragma("unroll")                                                  \
            for (int k = 0; k < K_; k++) {                                     \
                bool ok = act;                                                 \
                if ((PFMODE) == 0) ok = ok && (k >= 3 - (U));                  \
                sb[((U) + 3) & 3][k] =                                         \
                    ok ? __ldg(pe + ((U) + 3) * STEP_EL + (k - 6) * KOFF_EL)   \
                       : NEGBIG;                                               \
            }                                                                  \
        }                                                                      \
        {   /* part for step e+1: k-th term uses S_{e-5+k} = av[k+1] */        \
            float p0 = 0.f, p1 = 0.f, p2 = 0.f;                                \
            _Pragma("unroll")                                                  \
            for (int k = 0; k < K_ - 1; k++) {                                 \
                float f = ex2f(fmaf(sb[((U) + 1) & 3][k], LOG2E_F,             \
                                    msc[k + 1] - Mn));                         \
                float t = av[k + 1] * f;                                       \
                if (k % 3 == 0) p0 += t; else if (k % 3 == 1) p1 += t;         \
                else p2 += t;                                                  \
            }                                                                  \
            s_P[((U) + 1) & 1][y][yp] = (p0 + p1) + p2;                        \
        }                                                                      \
        /* f6 for step e+1: multiplies S_{e+1} (scale Mcur), new scale Mn */   \
        s_F6[((U) + 1) & 1][y][yp] =                                           \
            ex2f(fmaf(sb[((U) + 1) & 3][6], LOG2E_F, Mcur - Mn));              \
        Mprev = Mcur; Mcur = Mn;                                               \
        __syncthreads();                                                       \
    } while (0)

__global__ void __launch_bounds__(192, 1)
dp_kernel(const float* __restrict__ scores, const int* __restrict__ mask,
          float* __restrict__ out) {
    const int tid = threadIdx.x;
    const int y   = tid >> 4;      // 0..11 (y==11 -> idle segment)
    const int yp  = tid & 15;      // 0..15 (yp>=11 -> padding lanes)
    const bool act = (y < T_) && (yp < T_);

    __shared__ __align__(16) float s_Sring[8][16];  // S rows (linear)
    __shared__ __align__(16) float s_F6[2][12][16]; // f6 factors, dbl-buffered
    __shared__ __align__(16) float s_P[2][12][16];  // k<=5 partials, dbl-buf
    __shared__ float s_r[8];                        // log2 alpha[slot][0]

    if (tid < 8) s_r[tid] = 0.f;
    if (tid < 128) {
        int s = tid >> 4, c = tid & 15;
        s_Sring[s][c] = (s == 0 && c == (T_ - 1)) ? 1.f : 0.f;
    }

    const int len = mask[blockIdx.x];  // in [64, 128]
    const float* base =
        scores + (size_t)blockIdx.x * (L_ * L_ * TT_) + (yp * T_ + y);

    // score ring sb[e&3][k]; prefill e = 0,1,2 (compile-time j>=0 masks)
    float sb[4][K_];
#pragma unroll
    for (int ee = 0; ee < 3; ee++)
#pragma unroll
        for (int k = 0; k < K_; k++)
            sb[ee][k] = (act && (ee - 6 + k) >= 0)
                            ? __ldg(base + ee * STEP_EL + (k - 6) * KOFF_EL)
                            : NEGBIG;

    // parity-0 factor buffers for step 0: P = 0 (all k<=5 spans invalid),
    // F6 = exp2(score_0_k6 * log2e) (scale terms are 0); NEGBIG -> 0.
    s_P[0][y][yp]  = 0.f;
    s_F6[0][y][yp] = ex2f(sb[0][6] * LOG2E_F);

    // linear alpha window av[k] <-> S_{e-6+k}[yp]; msc[k] its scale
    float av[K_], msc[K_];
#pragma unroll
    for (int k = 0; k < K_; k++) { av[k] = 0.f; msc[k] = 0.f; }

    float Mcur  = 0.f;   // scale of S_1 (output of step 0)
    float Mprev = 0.f;   // scale of S_0
    float res   = 0.f;
    __syncthreads();

    // ── peeled first block: eb = 0 ──
    {
        const int eb = 0;
        const float* pe = base;
        DP_STEP(0, 0); DP_STEP(1, 0); DP_STEP(2, 0); DP_STEP(3, 0);
        DP_STEP(4, 0); DP_STEP(5, 0); DP_STEP(6, 0); DP_STEP(7, 0);
    }

    // ── steady state: eb = 8 .. 112 ──
    {
        const float* pe = base;
#pragma unroll 1
        for (int eb = 8; eb <= 112; eb += 8) {
            pe += 8 * STEP_EL;
            DP_STEP(0, 1); DP_STEP(1, 1); DP_STEP(2, 1); DP_STEP(3, 1);
            DP_STEP(4, 1); DP_STEP(5, 1); DP_STEP(6, 1); DP_STEP(7, 1);
        }
    }

    // ── peeled last block: eb = 120 ──
    {
        const int eb = 120;
        const float* pe = base + 120 * STEP_EL;
        DP_STEP(0, 2); DP_STEP(1, 2); DP_STEP(2, 2); DP_STEP(3, 2);
        DP_STEP(4, 2); DP_STEP(5, 2); DP_STEP(6, 2); DP_STEP(7, 2);
    }

    if (yp == 0 && y == T_ - 2) g_partial[blockIdx.x] = res * LN2_F;
    __syncthreads();

    // last-finishing block sums the 16 partials (no separate reduce launch)
    if (tid == 0) {
        __threadfence();
        unsigned old = atomicAdd(&g_tickets, 1u);
        if ((old & (B_ - 1)) == (B_ - 1)) {
            __threadfence();
            float s = 0.f;
#pragma unroll
            for (int bb = 0; bb < B_; bb++)
                s += *((volatile float*)&g_partial[bb]);
            out[0] = s;
        }
    }
}

extern "C" void kernel_launch(void* const* d_in, const int* in_sizes, int n_in,
                              void* d_out, int out_size) {
    const float* scores = (const float*)d_in[0];
    const int*   mask   = (const int*)d_in[1];

    dp_kernel<<<B_, 192>>>(scores, mask, (float*)d_out);
}

// round 16
// speedup vs baseline: 1.1848x; 1.1848x over previous
#include <cuda_runtime.h>
#include <cuda_bf16.h>

// Semi-CRF forward DP (HSCRF). B=16, L=128, T=11, K=7.
// R16: linear-domain publish (R13, exact) with MUFU-slack scheduling:
// f6 factors double-buffered (built 2 steps ahead; stale-4 target scales),
// part ex2s built 1 step ahead -> the post-barrier critical path is
// LDS S_e -> FFMA -> 4x shfl -> STS with NO MUFU and no queued-MUFU hazard.
// 192 thr, x8 unroll (compile-time slots), depth-3 prefetch, branch-free
// masking, in-kernel final reduction.

#define B_ 16
#define L_ 128
#define T_ 11
#define K_ 7
#define TT_ 121
#define NEGBIG  (-1e30f)
#define LOG2E_F 1.4426950408889634f
#define LN2_F   0.6931471805599453f
#define STEP_EL (129 * TT_)   /* elem offset per end-position step: 15609 */
#define KOFF_EL (128 * TT_)   /* elem offset per k: 15488 */

__device__ float g_partial[B_];
__device__ unsigned int g_tickets;   // one winner per launch (16 arrivals)

__device__ __forceinline__ float ex2f(float x) {
    float r; asm("ex2.approx.ftz.f32 %0, %1;" : "=f"(r) : "f"(x)); return r;
}
__device__ __forceinline__ float lg2f(float x) {
    float r; asm("lg2.approx.f32 %0, %1;" : "=f"(r) : "f"(x)); return r;
}

// One DP step at e = eb + U (computes S_{e+1}, scale MtgtA).
// PFMODE 0: first block (compile-time j>=0 masks on prefetch)
//        1: steady state (no masks)
//        2: last block (skip prefetch when e+3 >= L_, compile-time)
#define DP_STEP(U, PFMODE)                                                     \
    do {                                                                       \
        /* ── post-barrier critical path: no MUFU, no chained LDS ── */        \
        const float Se = s_S[(U)][yp];           /* S_e[yp] */                 \
        float acc = fmaf(Se, f6A, part);                                       \
        acc += __shfl_xor_sync(0xffffffffu, acc, 8, 16);                       \
        acc += __shfl_xor_sync(0xffffffffu, acc, 4, 16);                       \
        acc += __shfl_xor_sync(0xffffffffu, acc, 2, 16);                       \
        acc += __shfl_xor_sync(0xffffffffu, acc, 1, 16);                       \
        if (yp == 0) {                                                         \
            s_S[((U) + 1) & 7][y] = acc;         /* publish S_{e+1} FIRST */   \
            float an = MtgtA + lg2f(acc);        /* consumed >=4 bar later */  \
            if (y == 0) s_r[((U) + 1) & 7] = an;                               \
            if (y == T_ - 2 && (eb + (U) + 1) == len) res = an;                \
        }                                                                      \
        /* ── filler (all results have >=1 full step of slack) ── */           \
        const float rv = s_r[((U) + 4) & 7];     /* alpha_{e-4}[0] */          \
        _Pragma("unroll")                                                      \
        for (int k = 0; k < K_ - 1; k++) { av[k] = av[k + 1]; msc[k] = msc[k + 1]; } \
        av[K_ - 1]  = Se;                        /* S_e */                     \
        msc[K_ - 1] = MtgtPrev;                  /* scale of S_e */            \
        if ((PFMODE) != 2 || (U) < 5) {          /* prefetch scores e+3 */     \
            _Pragma("unroll")                                                  \
            for (int k = 0; k < K_; k++) {                                     \
                bool ok = act;                                                 \
                if ((PFMODE) == 0) ok = ok && (k >= 3 - (U));                  \
                sb[((U) + 3) & 3][k] =                                         \
                    ok ? __ldg(pe + ((U) + 3) * STEP_EL + (k - 6) * KOFF_EL)   \
                       : NEGBIG;                                               \
            }                                                                  \
        }                                                                      \
        {   /* part for step e+1 (target MtgtB): k-th term uses S_{e-5+k} */   \
            float p0 = 0.f, p1 = 0.f, p2 = 0.f;                                \
            _Pragma("unroll")                                                  \
            for (int k = 0; k < K_ - 1; k++) {                                 \
                float f = ex2f(fmaf(sb[((U) + 1) & 3][k], LOG2E_F,             \
                                    msc[k + 1] - MtgtB));                      \
                float t = av[k + 1] * f;                                       \
                if (k % 3 == 0) p0 += t; else if (k % 3 == 1) p1 += t;         \
                else p2 += t;                                                  \
            }                                                                  \
            part = (p0 + p1) + p2;                                             \
        }                                                                      \
        /* f6 for step e+2: multiplies S_{e+2} (scale MtgtB), target rv */     \
        f6A = f6B;                                                             \
        f6B = ex2f(fmaf(sb[((U) + 2) & 3][6], LOG2E_F, MtgtB - rv));           \
        MtgtPrev = MtgtA; MtgtA = MtgtB; MtgtB = rv;                           \
        __syncthreads();                                                       \
    } while (0)

__global__ void __launch_bounds__(192, 1)
dp_kernel(const float* __restrict__ scores, const int* __restrict__ mask,
          float* __restrict__ out) {
    const int tid = threadIdx.x;
    const int y   = tid >> 4;      // 0..11 (y==11 -> idle segment)
    const int yp  = tid & 15;      // 0..15 (yp>=11 -> padding lanes)
    const bool act = (y < T_) && (yp < T_);

    __shared__ float s_S[8][16];   // S rows (linear), [slot][label]
    __shared__ float s_r[8];       // log2 alpha[slot][0] (scale proxies)

    if (tid < 8) s_r[tid] = 0.f;
    if (tid < 128) {
        int s = tid >> 4, c = tid & 15;
        s_S[s][c] = (s == 0 && c == (T_ - 1)) ? 1.f : 0.f;  // S_0, scale 0
    }

    const int len = mask[blockIdx.x];  // in [64, 128]
    const float* base =
        scores + (size_t)blockIdx.x * (L_ * L_ * TT_) + (yp * T_ + y);

    // score ring sb[e&3][k]; prefill e = 0,1,2 (compile-time j>=0 masks)
    float sb[4][K_];
#pragma unroll
    for (int ee = 0; ee < 3; ee++)
#pragma unroll
        for (int k = 0; k < K_; k++)
            sb[ee][k] = (act && (ee - 6 + k) >= 0)
                            ? __ldg(base + ee * STEP_EL + (k - 6) * KOFF_EL)
                            : NEGBIG;

    // linear alpha window av[k] <-> S_{e-6+k}[yp]; msc[k] its scale
    float av[K_], msc[K_];
#pragma unroll
    for (int k = 0; k < K_; k++) { av[k] = 0.f; msc[k] = 0.f; }

    float part     = 0.f;   // step 0: all k<=5 spans invalid -> 0
    float MtgtPrev = 0.f;   // scale of S_0
    float MtgtA    = 0.f;   // scale of S_1
    float MtgtB    = 0.f;   // scale of S_2
    float res      = 0.f;
    // f6 for step 0 (mult S_0, scale 0, target 0) and step 1 (mult S_1)
    float f6A = ex2f(sb[0][6] * LOG2E_F);
    float f6B = ex2f(sb[1][6] * LOG2E_F);
    __syncthreads();

    // ── peeled first block: eb = 0 ──
    {
        const int eb = 0;
        const float* pe = base;
        DP_STEP(0, 0); DP_STEP(1, 0); DP_STEP(2, 0); DP_STEP(3, 0);
        DP_STEP(4, 0); DP_STEP(5, 0); DP_STEP(6, 0); DP_STEP(7, 0);
    }

    // ── steady state: eb = 8 .. 112 ──
    {
        const float* pe = base;
#pragma unroll 1
        for (int eb = 8; eb <= 112; eb += 8) {
            pe += 8 * STEP_EL;
            DP_STEP(0, 1); DP_STEP(1, 1); DP_STEP(2, 1); DP_STEP(3, 1);
            DP_STEP(4, 1); DP_STEP(5, 1); DP_STEP(6, 1); DP_STEP(7, 1);
        }
    }

    // ── peeled last block: eb = 120 ──
    {
        const int eb = 120;
        const float* pe = base + 120 * STEP_EL;
        DP_STEP(0, 2); DP_STEP(1, 2); DP_STEP(2, 2); DP_STEP(3, 2);
        DP_STEP(4, 2); DP_STEP(5, 2); DP_STEP(6, 2); DP_STEP(7, 2);
    }

    if (yp == 0 && y == T_ - 2) g_partial[blockIdx.x] = res * LN2_F;
    __syncthreads();

    // last-finishing block sums the 16 partials (no separate reduce launch)
    if (tid == 0) {
        __threadfence();
        unsigned old = atomicAdd(&g_tickets, 1u);
        if ((old & (B_ - 1)) == (B_ - 1)) {
            __threadfence();
            float s = 0.f;
#pragma unroll
            for (int bb = 0; bb < B_; bb++)
                s += *((volatile float*)&g_partial[bb]);
            out[0] = s;
        }
    }
}

extern "C" void kernel_launch(void* const* d_in, const int* in_sizes, int n_in,
                              void* d_out, int out_size) {
    const float* scores = (const float*)d_in[0];
    const int*   mask   = (const int*)d_in[1];

    dp_kernel<<<B_, 192>>>(scores, mask, (float*)d_out);
}

// round 17
// speedup vs baseline: 1.2194x; 1.0291x over previous
#include <cuda_runtime.h>
#include <cuda_bf16.h>

// Semi-CRF forward DP (HSCRF). B=16, L=128, T=11, K=7.
// R16: linear-domain publish (R13, exact) with MUFU-slack scheduling:
// f6 factors double-buffered (built 2 steps ahead; stale-4 target scales),
// part ex2s built 1 step ahead -> the post-barrier critical path is
// LDS S_e -> FFMA -> 4x shfl -> STS with NO MUFU and no queued-MUFU hazard.
// 192 thr, x8 unroll (compile-time slots), depth-3 prefetch, branch-free
// masking, in-kernel final reduction.

#define B_ 16
#define L_ 128
#define T_ 11
#define K_ 7
#define TT_ 121
#define NEGBIG  (-1e30f)
#define LOG2E_F 1.4426950408889634f
#define LN2_F   0.6931471805599453f
#define STEP_EL (129 * TT_)   /* elem offset per end-position step: 15609 */
#define KOFF_EL (128 * TT_)   /* elem offset per k: 15488 */

__device__ float g_partial[B_];
__device__ unsigned int g_tickets;   // one winner per launch (16 arrivals)

__device__ __forceinline__ float ex2f(float x) {
    float r; asm("ex2.approx.ftz.f32 %0, %1;" : "=f"(r) : "f"(x)); return r;
}
__device__ __forceinline__ float lg2f(float x) {
    float r; asm("lg2.approx.f32 %0, %1;" : "=f"(r) : "f"(x)); return r;
}

// One DP step at e = eb + U (computes S_{e+1}, scale MtgtA).
// PFMODE 0: first block (compile-time j>=0 masks on prefetch)
//        1: steady state (no masks)
//        2: last block (skip prefetch when e+3 >= L_, compile-time)
#define DP_STEP(U, PFMODE)                                                     \
    do {                                                                       \
        /* ── post-barrier critical path: no MUFU, no chained LDS ── */        \
        const float Se = s_S[(U)][yp];           /* S_e[yp] */                 \
        float acc = fmaf(Se, f6A, part);                                       \
        acc += __shfl_xor_sync(0xffffffffu, acc, 8, 16);                       \
        acc += __shfl_xor_sync(0xffffffffu, acc, 4, 16);                       \
        acc += __shfl_xor_sync(0xffffffffu, acc, 2, 16);                       \
        acc += __shfl_xor_sync(0xffffffffu, acc, 1, 16);                       \
        if (yp == 0) {                                                         \
            s_S[((U) + 1) & 7][y] = acc;         /* publish S_{e+1} FIRST */   \
            float an = MtgtA + lg2f(acc);        /* consumed >=4 bar later */  \
            if (y == 0) s_r[((U) + 1) & 7] = an;                               \
            if (y == T_ - 2 && (eb + (U) + 1) == len) res = an;                \
        }                                                                      \
        /* ── filler (all results have >=1 full step of slack) ── */           \
        const float rv = s_r[((U) + 4) & 7];     /* alpha_{e-4}[0] */          \
        _Pragma("unroll")                                                      \
        for (int k = 0; k < K_ - 1; k++) { av[k] = av[k + 1]; msc[k] = msc[k + 1]; } \
        av[K_ - 1]  = Se;                        /* S_e */                     \
        msc[K_ - 1] = MtgtPrev;                  /* scale of S_e */            \
        if ((PFMODE) != 2 || (U) < 5) {          /* prefetch scores e+3 */     \
            _Pragma("unroll")                                                  \
            for (int k = 0; k < K_; k++) {                                     \
                bool ok = act;                                                 \
                if ((PFMODE) == 0) ok = ok && (k >= 3 - (U));                  \
                sb[((U) + 3) & 3][k] =                                         \
                    ok ? __ldg(pe + ((U) + 3) * STEP_EL + (k - 6) * KOFF_EL)   \
                       : NEGBIG;                                               \
            }                                                                  \
        }                                                                      \
        {   /* part for step e+1 (target MtgtB): k-th term uses S_{e-5+k} */   \
            float p0 = 0.f, p1 = 0.f, p2 = 0.f;                                \
            _Pragma("unroll")                                                  \
            for (int k = 0; k < K_ - 1; k++) {                                 \
                float f = ex2f(fmaf(sb[((U) + 1) & 3][k], LOG2E_F,             \
                                    msc[k + 1] - MtgtB));                      \
                float t = av[k + 1] * f;                                       \
                if (k % 3 == 0) p0 += t; else if (k % 3 == 1) p1 += t;         \
                else p2 += t;                                                  \
            }                                                                  \
            part = (p0 + p1) + p2;                                             \
        }                                                                      \
        /* f6 for step e+2: multiplies S_{e+2} (scale MtgtB), target rv */     \
        f6A = f6B;                                                             \
        f6B = ex2f(fmaf(sb[((U) + 2) & 3][6], LOG2E_F, MtgtB - rv));           \
        MtgtPrev = MtgtA; MtgtA = MtgtB; MtgtB = rv;                           \
        __syncthreads();                                                       \
    } while (0)

__global__ void __launch_bounds__(192, 1)
dp_kernel(const float* __restrict__ scores, const int* __restrict__ mask,
          float* __restrict__ out) {
    const int tid = threadIdx.x;
    const int y   = tid >> 4;      // 0..11 (y==11 -> idle segment)
    const int yp  = tid & 15;      // 0..15 (yp>=11 -> padding lanes)
    const bool act = (y < T_) && (yp < T_);

    __shared__ float s_S[8][16];   // S rows (linear), [slot][label]
    __shared__ float s_r[8];       // log2 alpha[slot][0] (scale proxies)

    if (tid < 8) s_r[tid] = 0.f;
    if (tid < 128) {
        int s = tid >> 4, c = tid & 15;
        s_S[s][c] = (s == 0 && c == (T_ - 1)) ? 1.f : 0.f;  // S_0, scale 0
    }

    const int len = mask[blockIdx.x];  // in [64, 128]
    const float* base =
        scores + (size_t)blockIdx.x * (L_ * L_ * TT_) + (yp * T_ + y);

    // score ring sb[e&3][k]; prefill e = 0,1,2 (compile-time j>=0 masks)
    float sb[4][K_];
#pragma unroll
    for (int ee = 0; ee < 3; ee++)
#pragma unroll
        for (int k = 0; k < K_; k++)
            sb[ee][k] = (act && (ee - 6 + k) >= 0)
                            ? __ldg(base + ee * STEP_EL + (k - 6) * KOFF_EL)
                            : NEGBIG;

    // linear alpha window av[k] <-> S_{e-6+k}[yp]; msc[k] its scale
    float av[K_], msc[K_];
#pragma unroll
    for (int k = 0; k < K_; k++) { av[k] = 0.f; msc[k] = 0.f; }

    float part     = 0.f;   // step 0: all k<=5 spans invalid -> 0
    float MtgtPrev = 0.f;   // scale of S_0
    float MtgtA    = 0.f;   // scale of S_1
    float MtgtB    = 0.f;   // scale of S_2
    float res      = 0.f;
    // f6 for step 0 (mult S_0, scale 0, target 0) and step 1 (mult S_1)
    float f6A = ex2f(sb[0][6] * LOG2E_F);
    float f6B = ex2f(sb[1][6] * LOG2E_F);
    __syncthreads();

    // ── peeled first block: eb = 0 ──
    {
        const int eb = 0;
        const float* pe = base;
        DP_STEP(0, 0); DP_STEP(1, 0); DP_STEP(2, 0); DP_STEP(3, 0);
        DP_STEP(4, 0); DP_STEP(5, 0); DP_STEP(6, 0); DP_STEP(7, 0);
    }

    // ── steady state: eb = 8 .. 112 ──
    {
        const float* pe = base;
#pragma unroll 1
        for (int eb = 8; eb <= 112; eb += 8) {
            pe += 8 * STEP_EL;
            DP_STEP(0, 1); DP_STEP(1, 1); DP_STEP(2, 1); DP_STEP(3, 1);
            DP_STEP(4, 1); DP_STEP(5, 1); DP_STEP(6, 1); DP_STEP(7, 1);
        }
    }

    // ── peeled last block: eb = 120 ──
    {
        const int eb = 120;
        const float* pe = base + 120 * STEP_EL;
        DP_STEP(0, 2); DP_STEP(1, 2); DP_STEP(2, 2); DP_STEP(3, 2);
        DP_STEP(4, 2); DP_STEP(5, 2); DP_STEP(6, 2); DP_STEP(7, 2);
    }

    if (yp == 0 && y == T_ - 2) g_partial[blockIdx.x] = res * LN2_F;
    __syncthreads();

    // last-finishing block sums the 16 partials (no separate reduce launch)
    if (tid == 0) {
        __threadfence();
        unsigned old = atomicAdd(&g_tickets, 1u);
        if ((old & (B_ - 1)) == (B_ - 1)) {
            __threadfence();
            float s = 0.f;
#pragma unroll
            for (int bb = 0; bb < B_; bb++)
                s += *((volatile float*)&g_partial[bb]);
            out[0] = s;
        }
    }
}

extern "C" void kernel_launch(void* const* d_in, const int* in_sizes, int n_in,
                              void* d_out, int out_size) {
    const float* scores = (const float*)d_in[0];
    const int*   mask   = (const int*)d_in[1];

    dp_kernel<<<B_, 192>>>(scores, mask, (float*)d_out);
}